// round 14
// baseline (speedup 1.0000x reference)
#include <cuda_runtime.h>
#include <cstdint>

// Problem constants
#define BB 64
#define TT 1024
#define DD 512
#define BD (BB * DD)          // 32768
#define BTD ((size_t)BB * TT * DD)

// ---------------- scratch (no allocations allowed) ----------------
__device__ float g_xp[(size_t)TT * BB * DD];   // xproj, layout [t][b][e]
__device__ float g_m [(size_t)TT * BB * DD];   // m,     layout [t][b][e]
__device__ float g_tau[2][BD];                 // ping-pong tau state [b][e]
__device__ unsigned int g_flag[8 * 16 * 32];   // per-(b-group, e-tile) release flags, 128B apart

// ---------------- f32x2 packed-FMA helpers ----------------
__device__ __forceinline__ unsigned long long fma2(unsigned long long a,
                                                   unsigned long long b,
                                                   unsigned long long c)
{
    unsigned long long d;
    asm("fma.rn.f32x2 %0, %1, %2, %3;" : "=l"(d) : "l"(a), "l"(b), "l"(c));
    return d;
}
__device__ __forceinline__ unsigned long long pack2(float lo, float hi)
{
    unsigned long long r;
    asm("mov.b64 %0, {%1, %2};" : "=l"(r) : "f"(lo), "f"(hi));
    return r;
}
__device__ __forceinline__ float2 unpack2(unsigned long long v)
{
    float2 f;
    asm("mov.b64 {%0, %1}, %2;" : "=f"(f.x), "=f"(f.y) : "l"(v));
    return f;
}
__device__ __forceinline__ unsigned int ldacq(const unsigned int* p)
{
    unsigned int v;
    asm volatile("ld.acquire.gpu.u32 %0, [%1];" : "=r"(v) : "l"(p));
    return v;
}
__device__ __forceinline__ void strel(unsigned int* p, unsigned int v)
{
    asm volatile("st.release.gpu.u32 [%0], %1;" :: "l"(p), "r"(v) : "memory");
}

// =====================================================================
// Kernel 0: init (per-launch reset of release flags)
// =====================================================================
__global__ void __launch_bounds__(256) init_kernel()
{
#pragma unroll
    for (int i = threadIdx.x; i < 8 * 16 * 32; i += 256) g_flag[i] = 0u;
}

// =====================================================================
// Kernel 1: fused precompute GEMM, double-buffered smem (1 sync/iter)
//   out[r, n] = sum_k x[r,k] * W[n,k] + bias[n]
//   n <  512 : W = Wx  = tau_w[n, 0:512]   -> g_xp
//   n >= 512 : W = mem_w[n-512, :]         -> g_m
//   row r = b*T + t ; output written at [t][b][e]
// =====================================================================
__global__ void __launch_bounds__(256, 2) pre_gemm(
    const float* __restrict__ x,
    const float* __restrict__ tau_w,
    const float* __restrict__ tau_b,
    const float* __restrict__ mem_w,
    const float* __restrict__ mem_b)
{
    constexpr int Bk = 16;
    __shared__ float As[2][Bk][132];
    __shared__ float Bs[2][Bk][132];

    const int tid = threadIdx.x;
    const int m0 = blockIdx.y * 128;
    const int n0 = blockIdx.x * 128;

    const float* wbase;
    const float* bias;
    int rstride;
    float* outg;
    if (n0 < 512) { wbase = tau_w + (size_t)n0 * 1024; rstride = 1024; bias = tau_b + n0; outg = g_xp; }
    else          { wbase = mem_w + (size_t)(n0 - 512) * 512; rstride = 512; bias = mem_b + (n0 - 512); outg = g_m; }

    const int tm = tid >> 4;     // 0..15
    const int tn = tid & 15;     // 0..15

    const int lrow0 = (tid + 0)   >> 2;
    const int lkc0  = ((tid + 0) & 3) * 4;
    const int lrow1 = (tid + 256) >> 2;
    const int lkc1  = ((tid + 256) & 3) * 4;

    unsigned long long acc2[8][4];
#pragma unroll
    for (int i = 0; i < 8; i++)
#pragma unroll
        for (int p = 0; p < 4; p++) acc2[i][p] = 0ULL;

    float4 aR0, aR1, bR0, bR1;

    aR0 = *reinterpret_cast<const float4*>(&x[(size_t)(m0 + lrow0) * 512 + lkc0]);
    aR1 = *reinterpret_cast<const float4*>(&x[(size_t)(m0 + lrow1) * 512 + lkc1]);
    bR0 = *reinterpret_cast<const float4*>(&wbase[(size_t)lrow0 * rstride + lkc0]);
    bR1 = *reinterpret_cast<const float4*>(&wbase[(size_t)lrow1 * rstride + lkc1]);
    As[0][lkc0 + 0][lrow0] = aR0.x; As[0][lkc0 + 1][lrow0] = aR0.y;
    As[0][lkc0 + 2][lrow0] = aR0.z; As[0][lkc0 + 3][lrow0] = aR0.w;
    As[0][lkc1 + 0][lrow1] = aR1.x; As[0][lkc1 + 1][lrow1] = aR1.y;
    As[0][lkc1 + 2][lrow1] = aR1.z; As[0][lkc1 + 3][lrow1] = aR1.w;
    Bs[0][lkc0 + 0][lrow0] = bR0.x; Bs[0][lkc0 + 1][lrow0] = bR0.y;
    Bs[0][lkc0 + 2][lrow0] = bR0.z; Bs[0][lkc0 + 3][lrow0] = bR0.w;
    Bs[0][lkc1 + 0][lrow1] = bR1.x; Bs[0][lkc1 + 1][lrow1] = bR1.y;
    Bs[0][lkc1 + 2][lrow1] = bR1.z; Bs[0][lkc1 + 3][lrow1] = bR1.w;
    __syncthreads();

    for (int it = 0; it < 32; it++) {
        const int cur = it & 1;
        const int nxt = cur ^ 1;
        const bool hasNext = (it < 31);

        if (hasNext) {
            const int kk = (it + 1) * Bk;
            aR0 = *reinterpret_cast<const float4*>(&x[(size_t)(m0 + lrow0) * 512 + kk + lkc0]);
            aR1 = *reinterpret_cast<const float4*>(&x[(size_t)(m0 + lrow1) * 512 + kk + lkc1]);
            bR0 = *reinterpret_cast<const float4*>(&wbase[(size_t)lrow0 * rstride + kk + lkc0]);
            bR1 = *reinterpret_cast<const float4*>(&wbase[(size_t)lrow1 * rstride + kk + lkc1]);
        }

#pragma unroll
        for (int k = 0; k < Bk; k++) {
            float af[8];
            *reinterpret_cast<float4*>(&af[0]) = *reinterpret_cast<const float4*>(&As[cur][k][tm * 8]);
            *reinterpret_cast<float4*>(&af[4]) = *reinterpret_cast<const float4*>(&As[cur][k][tm * 8 + 4]);
            ulonglong2 b01 = *reinterpret_cast<const ulonglong2*>(&Bs[cur][k][tn * 8]);
            ulonglong2 b23 = *reinterpret_cast<const ulonglong2*>(&Bs[cur][k][tn * 8 + 4]);
#pragma unroll
            for (int i = 0; i < 8; i++) {
                unsigned long long a2 = pack2(af[i], af[i]);
                acc2[i][0] = fma2(a2, b01.x, acc2[i][0]);
                acc2[i][1] = fma2(a2, b01.y, acc2[i][1]);
                acc2[i][2] = fma2(a2, b23.x, acc2[i][2]);
                acc2[i][3] = fma2(a2, b23.y, acc2[i][3]);
            }
        }

        if (hasNext) {
            As[nxt][lkc0 + 0][lrow0] = aR0.x; As[nxt][lkc0 + 1][lrow0] = aR0.y;
            As[nxt][lkc0 + 2][lrow0] = aR0.z; As[nxt][lkc0 + 3][lrow0] = aR0.w;
            As[nxt][lkc1 + 0][lrow1] = aR1.x; As[nxt][lkc1 + 1][lrow1] = aR1.y;
            As[nxt][lkc1 + 2][lrow1] = aR1.z; As[nxt][lkc1 + 3][lrow1] = aR1.w;
            Bs[nxt][lkc0 + 0][lrow0] = bR0.x; Bs[nxt][lkc0 + 1][lrow0] = bR0.y;
            Bs[nxt][lkc0 + 2][lrow0] = bR0.z; Bs[nxt][lkc0 + 3][lrow0] = bR0.w;
            Bs[nxt][lkc1 + 0][lrow1] = bR1.x; Bs[nxt][lkc1 + 1][lrow1] = bR1.y;
            Bs[nxt][lkc1 + 2][lrow1] = bR1.z; Bs[nxt][lkc1 + 3][lrow1] = bR1.w;
        }
        __syncthreads();
    }

#pragma unroll
    for (int i = 0; i < 8; i++) {
        int r = m0 + tm * 8 + i;
        int b = r >> 10;
        int t = r & 1023;
        size_t rowoff = (size_t)t * BD + (size_t)b * DD;
#pragma unroll
        for (int p = 0; p < 4; p++) {
            float2 f = unpack2(acc2[i][p]);
            int n  = n0 + tn * 8 + 2 * p;
            outg[rowoff + ((n + 0) & 511)] = f.x + bias[tn * 8 + 2 * p + 0];
            outg[rowoff + ((n + 1) & 511)] = f.y + bias[tn * 8 + 2 * p + 1];
        }
    }
}

// =====================================================================
// Kernel 2: persistent scan, POINT-TO-POINT flag sync.
// 128 CTAs = 16 e-tiles(32e) x 8 b-groups(8b).
// Producer: CTA (eb,bb) release-stores flag[bb][eb]=t+1 after publishing
// its tau slice (single writer, no atomics).
// Consumer: warp kq needs tau k-slice [64kq,64kq+64) = output of e-tiles
// 2kq and 2kq+1 only -> polls exactly 2 flags, stages its slice, computes.
// Only two block-wide syncs per step remain (partials, publish).
// =====================================================================
__global__ void __launch_bounds__(256, 1) scan_kernel(
    const float* __restrict__ tau_w,
    const float* __restrict__ thr_p,
    float* __restrict__ out)
{
    __shared__ alignas(16) float tau_s[8 * 512];   // [b][k], warp-sliced by k
    __shared__ float red_s[8 * 8 * 32];            // [kq][bl][el] partials

    const int tid = threadIdx.x;
    const int eb = blockIdx.x & 15;        // e-tile
    const int bb = blockIdx.x >> 4;        // b-group
    const int e0 = eb * 32;
    const int b0 = bb * 8;

    const int kq = tid >> 5;               // warp id / k-slice of 64
    const int el = tid & 31;               // lane
    const int e  = e0 + el;
    const int k0 = kq * 64;

    // Wt[e, k0..k0+63] in registers as f32x2 (constant over steps)
    ulonglong2 wv2[16];
    {
        const ulonglong2* wrow = reinterpret_cast<const ulonglong2*>(
            tau_w + (size_t)e * 1024 + 512 + k0);
#pragma unroll
        for (int i = 0; i < 16; i++) wv2[i] = wrow[i];
    }

    // elementwise mapping: thread owns (pb, pe)
    const int pbl = tid >> 5;
    const int pel = tid & 31;
    const int pb = b0 + pbl;
    const int pe = e0 + pel;

    float v = 0.0f;
    const float thr = *thr_p;
    unsigned int* const myflag = &g_flag[(bb * 16 + eb) * 32];
    // this warp's two producer flags
    const unsigned int* const pf = &g_flag[(bb * 16 + kq * 2 + (el & 1)) * 32];

    float* out_spk = out;
    float* out_tau = out + BTD;
    float* out_v   = out + BTD + BD;

    // tau_0 = 1 in our warp's slice (warp-private)
#pragma unroll
    for (int bl = 0; bl < 8; bl++) {
        float2 one = make_float2(1.0f, 1.0f);
        *reinterpret_cast<float2*>(&tau_s[bl * 512 + k0 + 2 * el]) = one;
    }
    __syncwarp();

    float xpv = __ldcs(&g_xp[(size_t)pb * DD + pe]);
    float mv  = __ldcs(&g_m [(size_t)pb * DD + pe]);

    for (int t = 0; t < TT; t++) {
        // ---- compute partial dots from own tau_s slice (broadcast LDS) ----
        unsigned long long acc2[8];
#pragma unroll
        for (int bl = 0; bl < 8; bl++) acc2[bl] = 0ULL;
#pragma unroll
        for (int jq = 0; jq < 16; jq++) {
            const ulonglong2 w2 = wv2[jq];
#pragma unroll
            for (int bl = 0; bl < 8; bl++) {
                const ulonglong2 t2 = *reinterpret_cast<const ulonglong2*>(
                    &tau_s[bl * 512 + k0 + jq * 4]);
                acc2[bl] = fma2(w2.x, t2.x, acc2[bl]);
                acc2[bl] = fma2(w2.y, t2.y, acc2[bl]);
            }
        }
#pragma unroll
        for (int bl = 0; bl < 8; bl++) {
            float2 f = unpack2(acc2[bl]);
            red_s[kq * 256 + bl * 32 + el] = f.x + f.y;
        }
        __syncthreads();                             // #1 partials ready

        // ---- reduce + new tau ----
        float z = xpv;
#pragma unroll
        for (int q = 0; q < 8; q++) z += red_s[q * 256 + pbl * 32 + pel];
        const float ta = 1.0f / (1.0f + expf(-z));

        if (t == TT - 1) {
            const float al = expf(-1.0f / (ta + 1e-6f));
            v = al * v + (1.0f - al) * mv;
            const float s = (v >= thr) ? 1.0f : 0.0f;
            __stcs(&out_spk[(size_t)pb * TT * DD + (size_t)t * DD + pe], s);
            v = v * (1.0f - s);
            out_tau[pb * DD + pe] = ta;
            out_v  [pb * DD + pe] = v;
            break;
        }

        const int nxt = (t + 1) & 1;
        __stcg(&g_tau[nxt][pb * DD + pe], ta);       // publish ASAP
        __syncthreads();                             // #2 all stores issued
        if (tid == 0) strel(myflag, (unsigned)(t + 1));   // release own flag

        // ---- overlap window: elementwise + prefetch ----
        const float al = expf(-1.0f / (ta + 1e-6f));
        v = al * v + (1.0f - al) * mv;
        const float s = (v >= thr) ? 1.0f : 0.0f;
        __stcs(&out_spk[(size_t)pb * TT * DD + (size_t)t * DD + pe], s);
        v = v * (1.0f - s);
        {
            size_t goff = (size_t)(t + 1) * BD + (size_t)pb * DD + pe;
            xpv = __ldcs(&g_xp[goff]);
            mv  = __ldcs(&g_m[goff]);
        }

        // ---- per-warp wait on ONLY this warp's 2 producers ----
        if (el < 2) {
            while ((int)(ldacq(pf) - (unsigned)(t + 1)) < 0) {}
        }
        __syncwarp();

        // ---- warp-self-stage own slice of tau_{t+1} ----
#pragma unroll
        for (int bl = 0; bl < 8; bl++) {
            const float2 v2 = __ldcg(reinterpret_cast<const float2*>(
                &g_tau[nxt][(b0 + bl) * 512 + k0 + 2 * el]));
            *reinterpret_cast<float2*>(&tau_s[bl * 512 + k0 + 2 * el]) = v2;
        }
        __syncwarp();
    }
}

// =====================================================================
extern "C" void kernel_launch(void* const* d_in, const int* in_sizes, int n_in,
                              void* d_out, int out_size)
{
    const float* x     = (const float*)d_in[0];
    const float* tau_w = (const float*)d_in[1];
    const float* tau_b = (const float*)d_in[2];
    const float* mem_w = (const float*)d_in[3];
    const float* mem_b = (const float*)d_in[4];
    const float* thr   = (const float*)d_in[5];
    float* out = (float*)d_out;

    init_kernel<<<1, 256>>>();
    dim3 ggrid(8, 512);                 // N tiles x M tiles
    pre_gemm<<<ggrid, 256>>>(x, tau_w, tau_b, mem_w, mem_b);
    scan_kernel<<<128, 256>>>(tau_w, thr, out);
}

// round 15
// speedup vs baseline: 1.0045x; 1.0045x over previous
#include <cuda_runtime.h>
#include <cstdint>

// Problem constants
#define BB 64
#define TT 1024
#define DD 512
#define BD (BB * DD)          // 32768
#define BTD ((size_t)BB * TT * DD)

// ---------------- scratch (no allocations allowed) ----------------
__device__ float g_xp[(size_t)TT * BB * DD];   // xproj, layout [t][b][e]
__device__ float g_m [(size_t)TT * BB * DD];   // m,     layout [t][b][e]
__device__ float g_tau[2][BD];                 // ping-pong tau state [b][e]
__device__ unsigned int g_flag[8 * 16 * 32];   // per-(b-group, e-tile) release flags, 128B apart

// ---------------- f32x2 packed-FMA helpers ----------------
__device__ __forceinline__ unsigned long long fma2(unsigned long long a,
                                                   unsigned long long b,
                                                   unsigned long long c)
{
    unsigned long long d;
    asm("fma.rn.f32x2 %0, %1, %2, %3;" : "=l"(d) : "l"(a), "l"(b), "l"(c));
    return d;
}
__device__ __forceinline__ unsigned long long pack2(float lo, float hi)
{
    unsigned long long r;
    asm("mov.b64 %0, {%1, %2};" : "=l"(r) : "f"(lo), "f"(hi));
    return r;
}
__device__ __forceinline__ float2 unpack2(unsigned long long v)
{
    float2 f;
    asm("mov.b64 {%0, %1}, %2;" : "=f"(f.x), "=f"(f.y) : "l"(v));
    return f;
}
__device__ __forceinline__ unsigned int ldacq(const unsigned int* p)
{
    unsigned int v;
    asm volatile("ld.acquire.gpu.u32 %0, [%1];" : "=r"(v) : "l"(p));
    return v;
}
__device__ __forceinline__ void strel(unsigned int* p, unsigned int v)
{
    asm volatile("st.release.gpu.u32 [%0], %1;" :: "l"(p), "r"(v) : "memory");
}

// =====================================================================
// Kernel 0: init (per-launch reset of release flags)
// =====================================================================
__global__ void __launch_bounds__(256) init_kernel()
{
#pragma unroll
    for (int i = threadIdx.x; i < 8 * 16 * 32; i += 256) g_flag[i] = 0u;
}

// =====================================================================
// Kernel 1: fused precompute GEMM, double-buffered smem (1 sync/iter)
//   out[r, n] = sum_k x[r,k] * W[n,k] + bias[n]
//   n <  512 : W = Wx  = tau_w[n, 0:512]   -> g_xp
//   n >= 512 : W = mem_w[n-512, :]         -> g_m
//   row r = b*T + t ; output written at [t][b][e]
// =====================================================================
__global__ void __launch_bounds__(256, 2) pre_gemm(
    const float* __restrict__ x,
    const float* __restrict__ tau_w,
    const float* __restrict__ tau_b,
    const float* __restrict__ mem_w,
    const float* __restrict__ mem_b)
{
    constexpr int Bk = 16;
    __shared__ float As[2][Bk][132];
    __shared__ float Bs[2][Bk][132];

    const int tid = threadIdx.x;
    const int m0 = blockIdx.y * 128;
    const int n0 = blockIdx.x * 128;

    const float* wbase;
    const float* bias;
    int rstride;
    float* outg;
    if (n0 < 512) { wbase = tau_w + (size_t)n0 * 1024; rstride = 1024; bias = tau_b + n0; outg = g_xp; }
    else          { wbase = mem_w + (size_t)(n0 - 512) * 512; rstride = 512; bias = mem_b + (n0 - 512); outg = g_m; }

    const int tm = tid >> 4;     // 0..15
    const int tn = tid & 15;     // 0..15

    const int lrow0 = (tid + 0)   >> 2;
    const int lkc0  = ((tid + 0) & 3) * 4;
    const int lrow1 = (tid + 256) >> 2;
    const int lkc1  = ((tid + 256) & 3) * 4;

    unsigned long long acc2[8][4];
#pragma unroll
    for (int i = 0; i < 8; i++)
#pragma unroll
        for (int p = 0; p < 4; p++) acc2[i][p] = 0ULL;

    float4 aR0, aR1, bR0, bR1;

    aR0 = *reinterpret_cast<const float4*>(&x[(size_t)(m0 + lrow0) * 512 + lkc0]);
    aR1 = *reinterpret_cast<const float4*>(&x[(size_t)(m0 + lrow1) * 512 + lkc1]);
    bR0 = *reinterpret_cast<const float4*>(&wbase[(size_t)lrow0 * rstride + lkc0]);
    bR1 = *reinterpret_cast<const float4*>(&wbase[(size_t)lrow1 * rstride + lkc1]);
    As[0][lkc0 + 0][lrow0] = aR0.x; As[0][lkc0 + 1][lrow0] = aR0.y;
    As[0][lkc0 + 2][lrow0] = aR0.z; As[0][lkc0 + 3][lrow0] = aR0.w;
    As[0][lkc1 + 0][lrow1] = aR1.x; As[0][lkc1 + 1][lrow1] = aR1.y;
    As[0][lkc1 + 2][lrow1] = aR1.z; As[0][lkc1 + 3][lrow1] = aR1.w;
    Bs[0][lkc0 + 0][lrow0] = bR0.x; Bs[0][lkc0 + 1][lrow0] = bR0.y;
    Bs[0][lkc0 + 2][lrow0] = bR0.z; Bs[0][lkc0 + 3][lrow0] = bR0.w;
    Bs[0][lkc1 + 0][lrow1] = bR1.x; Bs[0][lkc1 + 1][lrow1] = bR1.y;
    Bs[0][lkc1 + 2][lrow1] = bR1.z; Bs[0][lkc1 + 3][lrow1] = bR1.w;
    __syncthreads();

    for (int it = 0; it < 32; it++) {
        const int cur = it & 1;
        const int nxt = cur ^ 1;
        const bool hasNext = (it < 31);

        if (hasNext) {
            const int kk = (it + 1) * Bk;
            aR0 = *reinterpret_cast<const float4*>(&x[(size_t)(m0 + lrow0) * 512 + kk + lkc0]);
            aR1 = *reinterpret_cast<const float4*>(&x[(size_t)(m0 + lrow1) * 512 + kk + lkc1]);
            bR0 = *reinterpret_cast<const float4*>(&wbase[(size_t)lrow0 * rstride + kk + lkc0]);
            bR1 = *reinterpret_cast<const float4*>(&wbase[(size_t)lrow1 * rstride + kk + lkc1]);
        }

#pragma unroll
        for (int k = 0; k < Bk; k++) {
            float af[8];
            *reinterpret_cast<float4*>(&af[0]) = *reinterpret_cast<const float4*>(&As[cur][k][tm * 8]);
            *reinterpret_cast<float4*>(&af[4]) = *reinterpret_cast<const float4*>(&As[cur][k][tm * 8 + 4]);
            ulonglong2 b01 = *reinterpret_cast<const ulonglong2*>(&Bs[cur][k][tn * 8]);
            ulonglong2 b23 = *reinterpret_cast<const ulonglong2*>(&Bs[cur][k][tn * 8 + 4]);
#pragma unroll
            for (int i = 0; i < 8; i++) {
                unsigned long long a2 = pack2(af[i], af[i]);
                acc2[i][0] = fma2(a2, b01.x, acc2[i][0]);
                acc2[i][1] = fma2(a2, b01.y, acc2[i][1]);
                acc2[i][2] = fma2(a2, b23.x, acc2[i][2]);
                acc2[i][3] = fma2(a2, b23.y, acc2[i][3]);
            }
        }

        if (hasNext) {
            As[nxt][lkc0 + 0][lrow0] = aR0.x; As[nxt][lkc0 + 1][lrow0] = aR0.y;
            As[nxt][lkc0 + 2][lrow0] = aR0.z; As[nxt][lkc0 + 3][lrow0] = aR0.w;
            As[nxt][lkc1 + 0][lrow1] = aR1.x; As[nxt][lkc1 + 1][lrow1] = aR1.y;
            As[nxt][lkc1 + 2][lrow1] = aR1.z; As[nxt][lkc1 + 3][lrow1] = aR1.w;
            Bs[nxt][lkc0 + 0][lrow0] = bR0.x; Bs[nxt][lkc0 + 1][lrow0] = bR0.y;
            Bs[nxt][lkc0 + 2][lrow0] = bR0.z; Bs[nxt][lkc0 + 3][lrow0] = bR0.w;
            Bs[nxt][lkc1 + 0][lrow1] = bR1.x; Bs[nxt][lkc1 + 1][lrow1] = bR1.y;
            Bs[nxt][lkc1 + 2][lrow1] = bR1.z; Bs[nxt][lkc1 + 3][lrow1] = bR1.w;
        }
        __syncthreads();
    }

#pragma unroll
    for (int i = 0; i < 8; i++) {
        int r = m0 + tm * 8 + i;
        int b = r >> 10;
        int t = r & 1023;
        size_t rowoff = (size_t)t * BD + (size_t)b * DD;
#pragma unroll
        for (int p = 0; p < 4; p++) {
            float2 f = unpack2(acc2[i][p]);
            int n  = n0 + tn * 8 + 2 * p;
            outg[rowoff + ((n + 0) & 511)] = f.x + bias[tn * 8 + 2 * p + 0];
            outg[rowoff + ((n + 1) & 511)] = f.y + bias[tn * 8 + 2 * p + 1];
        }
    }
}

// =====================================================================
// Kernel 2: persistent scan, POINT-TO-POINT flag sync.
// 128 CTAs = 16 e-tiles(32e) x 8 b-groups(8b).
// Producer: CTA (eb,bb) release-stores flag[bb][eb]=t+1 after publishing
// its tau slice (single writer, no atomics).
// Consumer: warp kq needs tau k-slice [64kq,64kq+64) = output of e-tiles
// 2kq and 2kq+1 only -> polls exactly 2 flags, stages its slice, computes.
// Only two block-wide syncs per step remain (partials, publish).
// =====================================================================
__global__ void __launch_bounds__(256, 1) scan_kernel(
    const float* __restrict__ tau_w,
    const float* __restrict__ thr_p,
    float* __restrict__ out)
{
    __shared__ alignas(16) float tau_s[8 * 512];   // [b][k], warp-sliced by k
    __shared__ float red_s[8 * 8 * 32];            // [kq][bl][el] partials

    const int tid = threadIdx.x;
    const int eb = blockIdx.x & 15;        // e-tile
    const int bb = blockIdx.x >> 4;        // b-group
    const int e0 = eb * 32;
    const int b0 = bb * 8;

    const int kq = tid >> 5;               // warp id / k-slice of 64
    const int el = tid & 31;               // lane
    const int e  = e0 + el;
    const int k0 = kq * 64;

    // Wt[e, k0..k0+63] in registers as f32x2 (constant over steps)
    ulonglong2 wv2[16];
    {
        const ulonglong2* wrow = reinterpret_cast<const ulonglong2*>(
            tau_w + (size_t)e * 1024 + 512 + k0);
#pragma unroll
        for (int i = 0; i < 16; i++) wv2[i] = wrow[i];
    }

    // elementwise mapping: thread owns (pb, pe)
    const int pbl = tid >> 5;
    const int pel = tid & 31;
    const int pb = b0 + pbl;
    const int pe = e0 + pel;

    float v = 0.0f;
    const float thr = *thr_p;
    unsigned int* const myflag = &g_flag[(bb * 16 + eb) * 32];
    // this warp's two producer flags
    const unsigned int* const pf = &g_flag[(bb * 16 + kq * 2 + (el & 1)) * 32];

    float* out_spk = out;
    float* out_tau = out + BTD;
    float* out_v   = out + BTD + BD;

    // tau_0 = 1 in our warp's slice (warp-private)
#pragma unroll
    for (int bl = 0; bl < 8; bl++) {
        float2 one = make_float2(1.0f, 1.0f);
        *reinterpret_cast<float2*>(&tau_s[bl * 512 + k0 + 2 * el]) = one;
    }
    __syncwarp();

    float xpv = __ldcs(&g_xp[(size_t)pb * DD + pe]);
    float mv  = __ldcs(&g_m [(size_t)pb * DD + pe]);

    for (int t = 0; t < TT; t++) {
        // ---- compute partial dots from own tau_s slice (broadcast LDS) ----
        unsigned long long acc2[8];
#pragma unroll
        for (int bl = 0; bl < 8; bl++) acc2[bl] = 0ULL;
#pragma unroll
        for (int jq = 0; jq < 16; jq++) {
            const ulonglong2 w2 = wv2[jq];
#pragma unroll
            for (int bl = 0; bl < 8; bl++) {
                const ulonglong2 t2 = *reinterpret_cast<const ulonglong2*>(
                    &tau_s[bl * 512 + k0 + jq * 4]);
                acc2[bl] = fma2(w2.x, t2.x, acc2[bl]);
                acc2[bl] = fma2(w2.y, t2.y, acc2[bl]);
            }
        }
#pragma unroll
        for (int bl = 0; bl < 8; bl++) {
            float2 f = unpack2(acc2[bl]);
            red_s[kq * 256 + bl * 32 + el] = f.x + f.y;
        }
        __syncthreads();                             // #1 partials ready

        // ---- reduce + new tau ----
        float z = xpv;
#pragma unroll
        for (int q = 0; q < 8; q++) z += red_s[q * 256 + pbl * 32 + pel];
        const float ta = 1.0f / (1.0f + expf(-z));

        if (t == TT - 1) {
            const float al = expf(-1.0f / (ta + 1e-6f));
            v = al * v + (1.0f - al) * mv;
            const float s = (v >= thr) ? 1.0f : 0.0f;
            __stcs(&out_spk[(size_t)pb * TT * DD + (size_t)t * DD + pe], s);
            v = v * (1.0f - s);
            out_tau[pb * DD + pe] = ta;
            out_v  [pb * DD + pe] = v;
            break;
        }

        const int nxt = (t + 1) & 1;
        __stcg(&g_tau[nxt][pb * DD + pe], ta);       // publish ASAP
        __syncthreads();                             // #2 all stores issued
        if (tid == 0) strel(myflag, (unsigned)(t + 1));   // release own flag

        // ---- overlap window: elementwise + prefetch ----
        const float al = expf(-1.0f / (ta + 1e-6f));
        v = al * v + (1.0f - al) * mv;
        const float s = (v >= thr) ? 1.0f : 0.0f;
        __stcs(&out_spk[(size_t)pb * TT * DD + (size_t)t * DD + pe], s);
        v = v * (1.0f - s);
        {
            size_t goff = (size_t)(t + 1) * BD + (size_t)pb * DD + pe;
            xpv = __ldcs(&g_xp[goff]);
            mv  = __ldcs(&g_m[goff]);
        }

        // ---- per-warp wait on ONLY this warp's 2 producers ----
        if (el < 2) {
            while ((int)(ldacq(pf) - (unsigned)(t + 1)) < 0) {}
        }
        __syncwarp();

        // ---- warp-self-stage own slice of tau_{t+1} ----
#pragma unroll
        for (int bl = 0; bl < 8; bl++) {
            const float2 v2 = __ldcg(reinterpret_cast<const float2*>(
                &g_tau[nxt][(b0 + bl) * 512 + k0 + 2 * el]));
            *reinterpret_cast<float2*>(&tau_s[bl * 512 + k0 + 2 * el]) = v2;
        }
        __syncwarp();
    }
}

// =====================================================================
extern "C" void kernel_launch(void* const* d_in, const int* in_sizes, int n_in,
                              void* d_out, int out_size)
{
    const float* x     = (const float*)d_in[0];
    const float* tau_w = (const float*)d_in[1];
    const float* tau_b = (const float*)d_in[2];
    const float* mem_w = (const float*)d_in[3];
    const float* mem_b = (const float*)d_in[4];
    const float* thr   = (const float*)d_in[5];
    float* out = (float*)d_out;

    init_kernel<<<1, 256>>>();
    dim3 ggrid(8, 512);                 // N tiles x M tiles
    pre_gemm<<<ggrid, 256>>>(x, tau_w, tau_b, mem_w, mem_b);
    scan_kernel<<<128, 256>>>(tau_w, thr, out);
}